// round 1
// baseline (speedup 1.0000x reference)
#include <cuda_runtime.h>

// Problem constants (fixed by the reference)
#define BB 4
#define SS 2048
#define DD 512
#define HH 8
#define HDIM 64
#define MTOT (BB * SS)  // 8192

// Scratch (device globals: allocation-free per harness rules). 4 x 16MB.
__device__ float g_Q[MTOT * DD];
__device__ float g_K[MTOT * DD];
__device__ float g_V[MTOT * DD];
__device__ float g_O[MTOT * DD];

// ---------------------------------------------------------------------------
// Generic GEMM: C[M,512] = A[M,512] @ W[512,512] + bias
// Block tile 64(M) x 128(N), K-tile 16, 256 threads, thread tile 4x8 (split 4+4)
// ---------------------------------------------------------------------------
__global__ __launch_bounds__(256)
void gemm_bias_kernel(const float* __restrict__ A, const float* __restrict__ W,
                      const float* __restrict__ bias, float* __restrict__ C)
{
    __shared__ float As[16 * 64];    // [k][m] (transposed)
    __shared__ float Bs[16 * 128];   // [k][n]

    const int n0 = blockIdx.x * 128;
    const int m0 = blockIdx.y * 64;
    const int tid = threadIdx.x;
    const int trow = tid >> 4;   // 0..15 -> rows trow*4..+3
    const int tcol = tid & 15;   // 0..15 -> cols tcol*4..+3 and +64

    float acc[4][8];
#pragma unroll
    for (int i = 0; i < 4; ++i)
#pragma unroll
        for (int j = 0; j < 8; ++j) acc[i][j] = 0.f;

    const int am = tid >> 2;           // 0..63
    const int ak4 = (tid & 3) << 2;    // 0,4,8,12

    for (int kt = 0; kt < DD; kt += 16) {
        // A tile 64x16 (store transposed)
        {
            float4 av = *(const float4*)&A[(m0 + am) * DD + kt + ak4];
            As[(ak4 + 0) * 64 + am] = av.x;
            As[(ak4 + 1) * 64 + am] = av.y;
            As[(ak4 + 2) * 64 + am] = av.z;
            As[(ak4 + 3) * 64 + am] = av.w;
        }
        // B tile 16x128
#pragma unroll
        for (int it = 0; it < 2; ++it) {
            int id = it * 256 + tid;
            int k = id >> 5;
            int n4 = (id & 31) << 2;
            *(float4*)&Bs[k * 128 + n4] = *(const float4*)&W[(kt + k) * DD + n0 + n4];
        }
        __syncthreads();
#pragma unroll
        for (int kk = 0; kk < 16; ++kk) {
            float4 a4 = *(const float4*)&As[kk * 64 + trow * 4];
            float4 b0 = *(const float4*)&Bs[kk * 128 + tcol * 4];
            float4 b1 = *(const float4*)&Bs[kk * 128 + 64 + tcol * 4];
            float aa[4] = {a4.x, a4.y, a4.z, a4.w};
            float bb[8] = {b0.x, b0.y, b0.z, b0.w, b1.x, b1.y, b1.z, b1.w};
#pragma unroll
            for (int i = 0; i < 4; ++i)
#pragma unroll
                for (int j = 0; j < 8; ++j) acc[i][j] += aa[i] * bb[j];
        }
        __syncthreads();
    }

    float4 bb0 = *(const float4*)&bias[n0 + tcol * 4];
    float4 bb1 = *(const float4*)&bias[n0 + 64 + tcol * 4];
#pragma unroll
    for (int i = 0; i < 4; ++i) {
        int row = m0 + trow * 4 + i;
        float4 r0 = make_float4(acc[i][0] + bb0.x, acc[i][1] + bb0.y,
                                acc[i][2] + bb0.z, acc[i][3] + bb0.w);
        float4 r1 = make_float4(acc[i][4] + bb1.x, acc[i][5] + bb1.y,
                                acc[i][6] + bb1.z, acc[i][7] + bb1.w);
        *(float4*)&C[row * DD + n0 + tcol * 4] = r0;
        *(float4*)&C[row * DD + n0 + 64 + tcol * 4] = r1;
    }
}

// ---------------------------------------------------------------------------
// Fused K/V/scale/shift: one pass over mod2, 4 accumulators.
//   K' = (mod2@Wk + bk) * (mod2@Ws + bs) + (mod2@Wsh + bsh)
//   V' = (mod2@Wv + bv) * (mod2@Ws + bs) + (mod2@Wsh + bsh)
// Block tile 64x64, K-tile 16, 256 threads, thread tile 4x4 per accumulator.
// ---------------------------------------------------------------------------
__global__ __launch_bounds__(256)
void kvss_kernel(const float* __restrict__ A,
                 const float* __restrict__ Wk, const float* __restrict__ Wv,
                 const float* __restrict__ Ws, const float* __restrict__ Wsh,
                 const float* __restrict__ bk, const float* __restrict__ bv,
                 const float* __restrict__ bs, const float* __restrict__ bsh)
{
    __shared__ float As[16 * 64];
    __shared__ float Bk[16 * 64];
    __shared__ float Bv[16 * 64];
    __shared__ float Bsc[16 * 64];
    __shared__ float Bsh[16 * 64];

    const int n0 = blockIdx.x * 64;
    const int m0 = blockIdx.y * 64;
    const int tid = threadIdx.x;
    const int trow = tid >> 4;
    const int tcol = tid & 15;

    float aK[4][4] = {}, aV[4][4] = {}, aS[4][4] = {}, aH[4][4] = {};

    const int am = tid >> 2;
    const int ak4 = (tid & 3) << 2;
    const int wk = tid >> 4;            // 0..15
    const int wn4 = (tid & 15) << 2;    // 0..60

    for (int kt = 0; kt < DD; kt += 16) {
        {
            float4 av = *(const float4*)&A[(m0 + am) * DD + kt + ak4];
            As[(ak4 + 0) * 64 + am] = av.x;
            As[(ak4 + 1) * 64 + am] = av.y;
            As[(ak4 + 2) * 64 + am] = av.z;
            As[(ak4 + 3) * 64 + am] = av.w;
        }
        int wi = (kt + wk) * DD + n0 + wn4;
        *(float4*)&Bk[wk * 64 + wn4]  = *(const float4*)&Wk[wi];
        *(float4*)&Bv[wk * 64 + wn4]  = *(const float4*)&Wv[wi];
        *(float4*)&Bsc[wk * 64 + wn4] = *(const float4*)&Ws[wi];
        *(float4*)&Bsh[wk * 64 + wn4] = *(const float4*)&Wsh[wi];
        __syncthreads();
#pragma unroll
        for (int kk = 0; kk < 16; ++kk) {
            float4 a4 = *(const float4*)&As[kk * 64 + trow * 4];
            float aa[4] = {a4.x, a4.y, a4.z, a4.w};
            float4 k4 = *(const float4*)&Bk[kk * 64 + tcol * 4];
            float4 v4 = *(const float4*)&Bv[kk * 64 + tcol * 4];
            float4 s4 = *(const float4*)&Bsc[kk * 64 + tcol * 4];
            float4 h4 = *(const float4*)&Bsh[kk * 64 + tcol * 4];
            float kb[4] = {k4.x, k4.y, k4.z, k4.w};
            float vb[4] = {v4.x, v4.y, v4.z, v4.w};
            float sb[4] = {s4.x, s4.y, s4.z, s4.w};
            float hb[4] = {h4.x, h4.y, h4.z, h4.w};
#pragma unroll
            for (int i = 0; i < 4; ++i)
#pragma unroll
                for (int j = 0; j < 4; ++j) {
                    aK[i][j] += aa[i] * kb[j];
                    aV[i][j] += aa[i] * vb[j];
                    aS[i][j] += aa[i] * sb[j];
                    aH[i][j] += aa[i] * hb[j];
                }
        }
        __syncthreads();
    }

    float4 cbk = *(const float4*)&bk[n0 + tcol * 4];
    float4 cbv = *(const float4*)&bv[n0 + tcol * 4];
    float4 cbs = *(const float4*)&bs[n0 + tcol * 4];
    float4 cbh = *(const float4*)&bsh[n0 + tcol * 4];
    float ck[4] = {cbk.x, cbk.y, cbk.z, cbk.w};
    float cv[4] = {cbv.x, cbv.y, cbv.z, cbv.w};
    float cs[4] = {cbs.x, cbs.y, cbs.z, cbs.w};
    float ch[4] = {cbh.x, cbh.y, cbh.z, cbh.w};

#pragma unroll
    for (int i = 0; i < 4; ++i) {
        int row = m0 + trow * 4 + i;
        float ko[4], vo[4];
#pragma unroll
        for (int j = 0; j < 4; ++j) {
            float kk_ = aK[i][j] + ck[j];
            float vv_ = aV[i][j] + cv[j];
            float sc  = aS[i][j] + cs[j];
            float sh  = aH[i][j] + ch[j];
            ko[j] = kk_ * sc + sh;
            vo[j] = vv_ * sc + sh;
        }
        *(float4*)&g_K[row * DD + n0 + tcol * 4] = make_float4(ko[0], ko[1], ko[2], ko[3]);
        *(float4*)&g_V[row * DD + n0 + tcol * 4] = make_float4(vo[0], vo[1], vo[2], vo[3]);
    }
}

// ---------------------------------------------------------------------------
// Flash attention, fp32. One block = (b, h, 64 q-rows). 256 threads.
// smem: Q[64x64] + T[64x64] (K^T swizzled, then V plain) + P[64x64] = 48KB.
// ---------------------------------------------------------------------------
__global__ __launch_bounds__(256)
void attn_kernel()
{
    __shared__ float Qs[64 * 64];
    __shared__ float Ts[64 * 64];
    __shared__ float Ps[64 * 64];

    const int b = blockIdx.z;
    const int h = blockIdx.y;
    const int q0 = blockIdx.x * 64;
    const int col0 = h * HDIM;
    const int rowbase = b * SS;
    const int tid = threadIdx.x;
    const int trow = tid >> 4;
    const int tcol = tid & 15;

    // Load Q tile
#pragma unroll
    for (int it = 0; it < 4; ++it) {
        int id = it * 256 + tid;
        int r = id >> 4;
        int c4 = (id & 15) << 2;
        *(float4*)&Qs[r * 64 + c4] =
            *(const float4*)&g_Q[(rowbase + q0 + r) * DD + col0 + c4];
    }

    float m_i[4], l_i[4], o[4][4];
#pragma unroll
    for (int i = 0; i < 4; ++i) {
        m_i[i] = -1e30f;
        l_i[i] = 0.f;
#pragma unroll
        for (int j = 0; j < 4; ++j) o[i][j] = 0.f;
    }

    for (int k0 = 0; k0 < SS; k0 += 64) {
        __syncthreads();  // previous iteration's readers of Ts/Ps done; Q ready (iter 0)

        // Load K tile transposed with XOR-group swizzle: logical (d, kc) ->
        // Ts[d*64 + 4*((kc>>2) ^ ((d>>2)&15)) + (kc&3)]
#pragma unroll
        for (int it = 0; it < 4; ++it) {
            int id = it * 256 + tid;
            int kc = id >> 4;
            int d4 = (id & 15) << 2;
            float4 v = *(const float4*)&g_K[(rowbase + k0 + kc) * DD + col0 + d4];
            int p = ((((kc >> 2) ^ ((d4 >> 2) & 15)) << 2) | (kc & 3));
            Ts[(d4 + 0) * 64 + p] = v.x;
            Ts[(d4 + 1) * 64 + p] = v.y;
            Ts[(d4 + 2) * 64 + p] = v.z;
            Ts[(d4 + 3) * 64 + p] = v.w;
        }
        __syncthreads();

        // S = Q @ K^T (4x4 micro tile per thread)
        float s[4][4];
#pragma unroll
        for (int i = 0; i < 4; ++i)
#pragma unroll
            for (int j = 0; j < 4; ++j) s[i][j] = 0.f;

#pragma unroll
        for (int d4 = 0; d4 < 64; d4 += 4) {
            float q[4][4];
#pragma unroll
            for (int i = 0; i < 4; ++i) {
                float4 t = *(const float4*)&Qs[(trow * 4 + i) * 64 + d4];
                q[i][0] = t.x; q[i][1] = t.y; q[i][2] = t.z; q[i][3] = t.w;
            }
            int pc = ((tcol ^ ((d4 >> 2) & 15)) << 2);
#pragma unroll
            for (int l = 0; l < 4; ++l) {
                float4 kb = *(const float4*)&Ts[(d4 + l) * 64 + pc];
#pragma unroll
                for (int i = 0; i < 4; ++i) {
                    s[i][0] += q[i][l] * kb.x;
                    s[i][1] += q[i][l] * kb.y;
                    s[i][2] += q[i][l] * kb.z;
                    s[i][3] += q[i][l] * kb.w;
                }
            }
        }

        // Online softmax (row groups = 16 threads, within half-warp)
        const float scale = 0.125f;  // 1/sqrt(64)
#pragma unroll
        for (int i = 0; i < 4; ++i) {
            float rm = -1e30f;
#pragma unroll
            for (int j = 0; j < 4; ++j) {
                s[i][j] *= scale;
                rm = fmaxf(rm, s[i][j]);
            }
#pragma unroll
            for (int off = 8; off > 0; off >>= 1)
                rm = fmaxf(rm, __shfl_xor_sync(0xffffffffu, rm, off, 16));
            float mn = fmaxf(m_i[i], rm);
            float alpha = __expf(m_i[i] - mn);
            m_i[i] = mn;
            float pv[4];
            float rs = 0.f;
#pragma unroll
            for (int j = 0; j < 4; ++j) {
                pv[j] = __expf(s[i][j] - mn);
                rs += pv[j];
            }
#pragma unroll
            for (int off = 8; off > 0; off >>= 1)
                rs += __shfl_xor_sync(0xffffffffu, rs, off, 16);
            l_i[i] = l_i[i] * alpha + rs;
#pragma unroll
            for (int j = 0; j < 4; ++j) o[i][j] *= alpha;
            *(float4*)&Ps[(trow * 4 + i) * 64 + tcol * 4] =
                make_float4(pv[0], pv[1], pv[2], pv[3]);
        }
        __syncthreads();  // Ts reads done, Ps visible

        // Load V tile (plain row-major) into Ts
#pragma unroll
        for (int it = 0; it < 4; ++it) {
            int id = it * 256 + tid;
            int kc = id >> 4;
            int d4 = (id & 15) << 2;
            *(float4*)&Ts[kc * 64 + d4] =
                *(const float4*)&g_V[(rowbase + k0 + kc) * DD + col0 + d4];
        }
        __syncthreads();

        // O += P @ V
#pragma unroll
        for (int k4 = 0; k4 < 64; k4 += 4) {
            float pr[4][4];
#pragma unroll
            for (int i = 0; i < 4; ++i) {
                float4 t = *(const float4*)&Ps[(trow * 4 + i) * 64 + k4];
                pr[i][0] = t.x; pr[i][1] = t.y; pr[i][2] = t.z; pr[i][3] = t.w;
            }
#pragma unroll
            for (int l = 0; l < 4; ++l) {
                float4 vv = *(const float4*)&Ts[(k4 + l) * 64 + tcol * 4];
#pragma unroll
                for (int i = 0; i < 4; ++i) {
                    o[i][0] += pr[i][l] * vv.x;
                    o[i][1] += pr[i][l] * vv.y;
                    o[i][2] += pr[i][l] * vv.z;
                    o[i][3] += pr[i][l] * vv.w;
                }
            }
        }
    }

    // Normalize and write output in [B, S, H*HD] layout
#pragma unroll
    for (int i = 0; i < 4; ++i) {
        float inv = 1.f / l_i[i];
        *(float4*)&g_O[(rowbase + q0 + trow * 4 + i) * DD + col0 + tcol * 4] =
            make_float4(o[i][0] * inv, o[i][1] * inv, o[i][2] * inv, o[i][3] * inv);
    }
}

// ---------------------------------------------------------------------------
extern "C" void kernel_launch(void* const* d_in, const int* in_sizes, int n_in,
                              void* d_out, int out_size)
{
    (void)in_sizes; (void)n_in; (void)out_size;

    const float* mod1 = (const float*)d_in[0];
    const float* mod2 = (const float*)d_in[1];
    const float* Wq  = (const float*)d_in[2];  const float* bq  = (const float*)d_in[3];
    const float* Wk  = (const float*)d_in[4];  const float* bk  = (const float*)d_in[5];
    const float* Wv  = (const float*)d_in[6];  const float* bv  = (const float*)d_in[7];
    const float* Wo  = (const float*)d_in[8];  const float* bo  = (const float*)d_in[9];
    const float* Ws  = (const float*)d_in[10]; const float* bs  = (const float*)d_in[11];
    const float* Wsh = (const float*)d_in[12]; const float* bsh = (const float*)d_in[13];
    float* out = (float*)d_out;

    float* pQ = nullptr;
    float* pO = nullptr;
    cudaGetSymbolAddress((void**)&pQ, g_Q);
    cudaGetSymbolAddress((void**)&pO, g_O);

    dim3 gGemm(DD / 128, MTOT / 64);   // (4, 128)
    gemm_bias_kernel<<<gGemm, 256>>>(mod1, Wq, bq, pQ);
    kvss_kernel<<<dim3(DD / 64, MTOT / 64), 256>>>(mod2, Wk, Wv, Ws, Wsh,
                                                   bk, bv, bs, bsh);
    attn_kernel<<<dim3(SS / 64, HH, BB), 256>>>();
    gemm_bias_kernel<<<gGemm, 256>>>(pO, Wo, bo, out);
}

// round 2
// speedup vs baseline: 1.7628x; 1.7628x over previous
#include <cuda_runtime.h>
#include <cuda_bf16.h>
#include <cstdint>

// Problem constants
#define BB 4
#define SS 2048
#define DD 512
#define HH 8
#define HDIM 64
#define MTOT (BB * SS)  // 8192

// Scratch buffers (device globals; allocation-free per harness rules)
__device__ float g_Q[MTOT * DD];
__device__ float g_K[MTOT * DD];
__device__ float g_V[MTOT * DD];
__device__ float g_S[MTOT * DD];
__device__ float g_H[MTOT * DD];
__device__ float g_O[MTOT * DD];

// ---------------------------------------------------------------------------
// Helpers: bf16 hi/lo split (x = hi + lo, each bf16) packed as {e0,e1} in u32
// ---------------------------------------------------------------------------
__device__ __forceinline__ void split2(float x0, float x1,
                                       uint32_t& hi, uint32_t& lo)
{
    __nv_bfloat16 h0 = __float2bfloat16(x0);
    __nv_bfloat16 h1 = __float2bfloat16(x1);
    float r0 = x0 - __bfloat162float(h0);
    float r1 = x1 - __bfloat162float(h1);
    __nv_bfloat16 l0 = __float2bfloat16(r0);
    __nv_bfloat16 l1 = __float2bfloat16(r1);
    __nv_bfloat162 H; H.x = h0; H.y = h1;
    __nv_bfloat162 L; L.x = l0; L.y = l1;
    hi = *reinterpret_cast<uint32_t*>(&H);
    lo = *reinterpret_cast<uint32_t*>(&L);
}

// mma.m16n8k16 bf16, fp32 accumulate, D == C in place
__device__ __forceinline__ void mma16816(float c[4],
                                         uint32_t a0, uint32_t a1, uint32_t a2, uint32_t a3,
                                         uint32_t b0, uint32_t b1)
{
    asm volatile(
        "mma.sync.aligned.m16n8k16.row.col.f32.bf16.bf16.f32 "
        "{%0,%1,%2,%3}, {%4,%5,%6,%7}, {%8,%9}, {%0,%1,%2,%3};\n"
        : "+f"(c[0]), "+f"(c[1]), "+f"(c[2]), "+f"(c[3])
        : "r"(a0), "r"(a1), "r"(a2), "r"(a3), "r"(b0), "r"(b1));
}

// ---------------------------------------------------------------------------
// GEMM: C[M,512] = A[M,512] @ W[512,512] + bias, bf16x3 emulation.
// Block 128x128, 256 threads (8 warps, 2x4), warp tile 64x32, ktile 16.
// ---------------------------------------------------------------------------
#define GM_LDA 12    // u32 per A-row (8 k-pairs + pad 4)
#define GM_LDB 136   // u32 per B kp-row (128 n + pad 8)

__global__ __launch_bounds__(256)
void gemm_bf16x3(const float* __restrict__ A, const float* __restrict__ W,
                 const float* __restrict__ bias, float* __restrict__ C)
{
    __shared__ uint32_t Ah[2][128 * GM_LDA];
    __shared__ uint32_t Al[2][128 * GM_LDA];
    __shared__ uint32_t Bh[2][8 * GM_LDB];
    __shared__ uint32_t Bl[2][8 * GM_LDB];

    const int m0 = blockIdx.y * 128;
    const int n0b = blockIdx.x * 128;
    const int tid = threadIdx.x;
    const int warp = tid >> 5;
    const int lane = tid & 31;
    const int g = lane >> 2;     // group id (row within 8)
    const int tig = lane & 3;    // thread in group
    const int wm = (warp >> 2) * 64;   // 0 or 64
    const int wn = (warp & 3) * 32;    // 0,32,64,96

    float acc[4][4][4];
#pragma unroll
    for (int mt = 0; mt < 4; ++mt)
#pragma unroll
        for (int nt = 0; nt < 4; ++nt)
#pragma unroll
            for (int r = 0; r < 4; ++r) acc[mt][nt][r] = 0.f;

    // tile fill lambdas
    auto loadA = [&](int kt, int buf) {
#pragma unroll
        for (int it = 0; it < 2; ++it) {
            int id = it * 256 + tid;
            int r = id >> 2;
            int k4 = (id & 3) << 2;
            float4 v = *(const float4*)&A[(m0 + r) * DD + kt + k4];
            uint32_t h0, l0, h1, l1;
            split2(v.x, v.y, h0, l0);
            split2(v.z, v.w, h1, l1);
            int base = r * GM_LDA + (k4 >> 1);
            Ah[buf][base]     = h0;  Ah[buf][base + 1] = h1;
            Al[buf][base]     = l0;  Al[buf][base + 1] = l1;
        }
    };
    auto loadB = [&](int kt, int buf) {
        int kp = tid >> 5;              // 0..7
        int n4 = (lane) << 2;           // 0..124
        const float* w0 = &W[(kt + 2 * kp) * DD + n0b + n4];
        float4 r0 = *(const float4*)w0;
        float4 r1 = *(const float4*)(w0 + DD);
        int base = kp * GM_LDB + n4;
        uint32_t h, l;
        split2(r0.x, r1.x, h, l); Bh[buf][base + 0] = h; Bl[buf][base + 0] = l;
        split2(r0.y, r1.y, h, l); Bh[buf][base + 1] = h; Bl[buf][base + 1] = l;
        split2(r0.z, r1.z, h, l); Bh[buf][base + 2] = h; Bl[buf][base + 2] = l;
        split2(r0.w, r1.w, h, l); Bh[buf][base + 3] = h; Bl[buf][base + 3] = l;
    };

    loadA(0, 0);
    loadB(0, 0);
    __syncthreads();

    for (int kt = 0; kt < DD; kt += 16) {
        const int buf = (kt >> 4) & 1;
        if (kt + 16 < DD) {
            loadA(kt + 16, buf ^ 1);
            loadB(kt + 16, buf ^ 1);
        }

        // fragment loads
        uint32_t ah[4][4], al[4][4], bh[4][2], bl[4][2];
#pragma unroll
        for (int mt = 0; mt < 4; ++mt) {
            int r0i = (wm + mt * 16 + g) * GM_LDA;
            int r1i = (wm + mt * 16 + g + 8) * GM_LDA;
            ah[mt][0] = Ah[buf][r0i + tig];
            ah[mt][1] = Ah[buf][r1i + tig];
            ah[mt][2] = Ah[buf][r0i + tig + 4];
            ah[mt][3] = Ah[buf][r1i + tig + 4];
            al[mt][0] = Al[buf][r0i + tig];
            al[mt][1] = Al[buf][r1i + tig];
            al[mt][2] = Al[buf][r0i + tig + 4];
            al[mt][3] = Al[buf][r1i + tig + 4];
        }
#pragma unroll
        for (int nt = 0; nt < 4; ++nt) {
            int col = wn + nt * 8 + g;
            bh[nt][0] = Bh[buf][tig * GM_LDB + col];
            bh[nt][1] = Bh[buf][(tig + 4) * GM_LDB + col];
            bl[nt][0] = Bl[buf][tig * GM_LDB + col];
            bl[nt][1] = Bl[buf][(tig + 4) * GM_LDB + col];
        }
#pragma unroll
        for (int mt = 0; mt < 4; ++mt)
#pragma unroll
            for (int nt = 0; nt < 4; ++nt) {
                mma16816(acc[mt][nt], ah[mt][0], ah[mt][1], ah[mt][2], ah[mt][3],
                         bh[nt][0], bh[nt][1]);
                mma16816(acc[mt][nt], ah[mt][0], ah[mt][1], ah[mt][2], ah[mt][3],
                         bl[nt][0], bl[nt][1]);
                mma16816(acc[mt][nt], al[mt][0], al[mt][1], al[mt][2], al[mt][3],
                         bh[nt][0], bh[nt][1]);
            }
        __syncthreads();
    }

    // epilogue: bias + store
#pragma unroll
    for (int mt = 0; mt < 4; ++mt) {
        int row0 = m0 + wm + mt * 16 + g;
        int row1 = row0 + 8;
#pragma unroll
        for (int nt = 0; nt < 4; ++nt) {
            int col = n0b + wn + nt * 8 + 2 * tig;
            float b0 = bias[col], b1 = bias[col + 1];
            float2 v0 = make_float2(acc[mt][nt][0] + b0, acc[mt][nt][1] + b1);
            float2 v1 = make_float2(acc[mt][nt][2] + b0, acc[mt][nt][3] + b1);
            *(float2*)&C[row0 * DD + col] = v0;
            *(float2*)&C[row1 * DD + col] = v1;
        }
    }
}

// ---------------------------------------------------------------------------
// Elementwise: K = K*s + h ; V = V*s + h   (in place)
// ---------------------------------------------------------------------------
__global__ __launch_bounds__(256)
void kvss_epilogue(float* __restrict__ K, float* __restrict__ V,
                   const float* __restrict__ S, const float* __restrict__ H)
{
    int i = (blockIdx.x * 256 + threadIdx.x) * 4;
    float4 k = *(float4*)&K[i];
    float4 v = *(float4*)&V[i];
    float4 s = *(const float4*)&S[i];
    float4 h = *(const float4*)&H[i];
    k.x = k.x * s.x + h.x; k.y = k.y * s.y + h.y;
    k.z = k.z * s.z + h.z; k.w = k.w * s.w + h.w;
    v.x = v.x * s.x + h.x; v.y = v.y * s.y + h.y;
    v.z = v.z * s.z + h.z; v.w = v.w * s.w + h.w;
    *(float4*)&K[i] = k;
    *(float4*)&V[i] = v;
}

// ---------------------------------------------------------------------------
// Flash attention on bf16x3 mma. Block = (b, h, 64 q rows), 128 threads
// (4 warps x 16 q rows). Key chunk 64. Q fragments register-resident.
// smem: T (K^T pairs [dp][key] then V pairs [kp][d]) + P pairs [q][kp].
// ---------------------------------------------------------------------------
#define AT_LDT 72   // u32 per pair-row of T (64 + pad 8)
#define AT_LDP 36   // u32 per P row (32 pairs + pad 4)

__global__ __launch_bounds__(128)
void attn_bf16x3(const float* __restrict__ Q, const float* __restrict__ K,
                 const float* __restrict__ V, float* __restrict__ O)
{
    __shared__ uint32_t Th[32 * AT_LDT];
    __shared__ uint32_t Tl[32 * AT_LDT];
    __shared__ uint32_t Ph[64 * AT_LDP];
    __shared__ uint32_t Pl[64 * AT_LDP];

    const int b = blockIdx.z;
    const int h = blockIdx.y;
    const int q0 = blockIdx.x * 64;
    const int rowbase = b * SS;
    const int col0 = h * HDIM;
    const int tid = threadIdx.x;
    const int warp = tid >> 5;
    const int lane = tid & 31;
    const int g = lane >> 2;
    const int tig = lane & 3;

    // --- load Q fragments to registers (hi/lo), 4 k16-steps over d=64 ---
    uint32_t qh[4][4], ql[4][4];
    {
        const float* qp0 = &Q[(rowbase + q0 + warp * 16 + g) * DD + col0];
        const float* qp1 = qp0 + 8 * DD;
#pragma unroll
        for (int s = 0; s < 4; ++s) {
            float2 x0 = *(const float2*)&qp0[16 * s + 2 * tig];
            float2 x1 = *(const float2*)&qp1[16 * s + 2 * tig];
            float2 x2 = *(const float2*)&qp0[16 * s + 2 * tig + 8];
            float2 x3 = *(const float2*)&qp1[16 * s + 2 * tig + 8];
            split2(x0.x, x0.y, qh[s][0], ql[s][0]);
            split2(x1.x, x1.y, qh[s][1], ql[s][1]);
            split2(x2.x, x2.y, qh[s][2], ql[s][2]);
            split2(x3.x, x3.y, qh[s][3], ql[s][3]);
        }
    }

    float o[8][4];
#pragma unroll
    for (int nt = 0; nt < 8; ++nt)
#pragma unroll
        for (int r = 0; r < 4; ++r) o[nt][r] = 0.f;
    float mA = -1e30f, mB = -1e30f, lA = 0.f, lB = 0.f;

    for (int kc = 0; kc < SS; kc += 64) {
        __syncthreads();  // V readers of previous chunk done

        // ---- fill K^T pairs: Th[dp][key] = {K[key][2dp], K[key][2dp+1]} ----
        {
            int key = tid & 63;
            int dhalf = tid >> 6;  // 0/1
            const float* kp_ = &K[(rowbase + kc + key) * DD + col0];
#pragma unroll
            for (int j = 0; j < 8; ++j) {
                int d4 = dhalf * 4 + j * 8;
                float4 v = *(const float4*)&kp_[d4];
                uint32_t h0, l0, h1, l1;
                split2(v.x, v.y, h0, l0);
                split2(v.z, v.w, h1, l1);
                int dp = d4 >> 1;
                Th[dp * AT_LDT + key] = h0;  Tl[dp * AT_LDT + key] = l0;
                Th[(dp + 1) * AT_LDT + key] = h1;  Tl[(dp + 1) * AT_LDT + key] = l1;
            }
        }
        __syncthreads();

        // ---- S = Q @ K^T (bf16x3) ----
        float s[8][4];
#pragma unroll
        for (int nt = 0; nt < 8; ++nt)
#pragma unroll
            for (int r = 0; r < 4; ++r) s[nt][r] = 0.f;

#pragma unroll
        for (int ks = 0; ks < 4; ++ks) {
#pragma unroll
            for (int nt = 0; nt < 8; ++nt) {
                int colk = nt * 8 + g;
                uint32_t b0h = Th[(8 * ks + tig) * AT_LDT + colk];
                uint32_t b1h = Th[(8 * ks + tig + 4) * AT_LDT + colk];
                uint32_t b0l = Tl[(8 * ks + tig) * AT_LDT + colk];
                uint32_t b1l = Tl[(8 * ks + tig + 4) * AT_LDT + colk];
                mma16816(s[nt], qh[ks][0], qh[ks][1], qh[ks][2], qh[ks][3], b0h, b1h);
                mma16816(s[nt], qh[ks][0], qh[ks][1], qh[ks][2], qh[ks][3], b0l, b1l);
                mma16816(s[nt], ql[ks][0], ql[ks][1], ql[ks][2], ql[ks][3], b0h, b1h);
            }
        }

        // ---- online softmax (rows g and g+8 per thread) ----
        const float sc = 0.125f;  // 1/sqrt(64)
        float rmA = -1e30f, rmB = -1e30f;
#pragma unroll
        for (int nt = 0; nt < 8; ++nt) {
            s[nt][0] *= sc; s[nt][1] *= sc; s[nt][2] *= sc; s[nt][3] *= sc;
            rmA = fmaxf(rmA, fmaxf(s[nt][0], s[nt][1]));
            rmB = fmaxf(rmB, fmaxf(s[nt][2], s[nt][3]));
        }
        rmA = fmaxf(rmA, __shfl_xor_sync(0xffffffffu, rmA, 1));
        rmA = fmaxf(rmA, __shfl_xor_sync(0xffffffffu, rmA, 2));
        rmB = fmaxf(rmB, __shfl_xor_sync(0xffffffffu, rmB, 1));
        rmB = fmaxf(rmB, __shfl_xor_sync(0xffffffffu, rmB, 2));

        float mnA = fmaxf(mA, rmA);
        float mnB = fmaxf(mB, rmB);
        float alA = __expf(mA - mnA);
        float alB = __expf(mB - mnB);
        mA = mnA; mB = mnB;

        float sumA = 0.f, sumB = 0.f;
        int prow0 = (warp * 16 + g) * AT_LDP;
        int prow1 = (warp * 16 + g + 8) * AT_LDP;
#pragma unroll
        for (int nt = 0; nt < 8; ++nt) {
            float p0 = __expf(s[nt][0] - mA);
            float p1 = __expf(s[nt][1] - mA);
            float p2 = __expf(s[nt][2] - mB);
            float p3 = __expf(s[nt][3] - mB);
            sumA += p0 + p1;
            sumB += p2 + p3;
            uint32_t hh, ll;
            split2(p0, p1, hh, ll);
            Ph[prow0 + nt * 4 + tig] = hh;  Pl[prow0 + nt * 4 + tig] = ll;
            split2(p2, p3, hh, ll);
            Ph[prow1 + nt * 4 + tig] = hh;  Pl[prow1 + nt * 4 + tig] = ll;
        }
        sumA += __shfl_xor_sync(0xffffffffu, sumA, 1);
        sumA += __shfl_xor_sync(0xffffffffu, sumA, 2);
        sumB += __shfl_xor_sync(0xffffffffu, sumB, 1);
        sumB += __shfl_xor_sync(0xffffffffu, sumB, 2);
        lA = lA * alA + sumA;
        lB = lB * alB + sumB;
#pragma unroll
        for (int nt = 0; nt < 8; ++nt) {
            o[nt][0] *= alA; o[nt][1] *= alA;
            o[nt][2] *= alB; o[nt][3] *= alB;
        }
        __syncthreads();  // K reads done; P visible

        // ---- fill V pairs: Th[kp][d] = {V[2kp][d], V[2kp+1][d]} ----
        {
            int dq = (tid & 15) << 2;   // 0..60
            int kph = tid >> 4;         // 0..7
#pragma unroll
            for (int j = 0; j < 4; ++j) {
                int kp = kph + j * 8;   // 0..31
                const float* vp = &V[(rowbase + kc + 2 * kp) * DD + col0 + dq];
                float4 r0 = *(const float4*)vp;
                float4 r1 = *(const float4*)(vp + DD);
                int base = kp * AT_LDT + dq;
                uint32_t hh, ll;
                split2(r0.x, r1.x, hh, ll); Th[base + 0] = hh; Tl[base + 0] = ll;
                split2(r0.y, r1.y, hh, ll); Th[base + 1] = hh; Tl[base + 1] = ll;
                split2(r0.z, r1.z, hh, ll); Th[base + 2] = hh; Tl[base + 2] = ll;
                split2(r0.w, r1.w, hh, ll); Th[base + 3] = hh; Tl[base + 3] = ll;
            }
        }
        __syncthreads();

        // ---- O += P @ V (bf16x3) ----
#pragma unroll
        for (int ks = 0; ks < 4; ++ks) {
            uint32_t pah[4], pal[4];
            pah[0] = Ph[prow0 + 8 * ks + tig];
            pah[1] = Ph[prow1 + 8 * ks + tig];
            pah[2] = Ph[prow0 + 8 * ks + tig + 4];
            pah[3] = Ph[prow1 + 8 * ks + tig + 4];
            pal[0] = Pl[prow0 + 8 * ks + tig];
            pal[1] = Pl[prow1 + 8 * ks + tig];
            pal[2] = Pl[prow0 + 8 * ks + tig + 4];
            pal[3] = Pl[prow1 + 8 * ks + tig + 4];
#pragma unroll
            for (int nt = 0; nt < 8; ++nt) {
                int cold = nt * 8 + g;
                uint32_t b0h = Th[(8 * ks + tig) * AT_LDT + cold];
                uint32_t b1h = Th[(8 * ks + tig + 4) * AT_LDT + cold];
                uint32_t b0l = Tl[(8 * ks + tig) * AT_LDT + cold];
                uint32_t b1l = Tl[(8 * ks + tig + 4) * AT_LDT + cold];
                mma16816(o[nt], pah[0], pah[1], pah[2], pah[3], b0h, b1h);
                mma16816(o[nt], pah[0], pah[1], pah[2], pah[3], b0l, b1l);
                mma16816(o[nt], pal[0], pal[1], pal[2], pal[3], b0h, b1h);
            }
        }
    }

    // ---- normalize + store ----
    float invA = 1.f / lA;
    float invB = 1.f / lB;
    int r0g = rowbase + q0 + warp * 16 + g;
#pragma unroll
    for (int nt = 0; nt < 8; ++nt) {
        int col = col0 + nt * 8 + 2 * tig;
        *(float2*)&O[r0g * DD + col] =
            make_float2(o[nt][0] * invA, o[nt][1] * invA);
        *(float2*)&O[(r0g + 8) * DD + col] =
            make_float2(o[nt][2] * invB, o[nt][3] * invB);
    }
}

// ---------------------------------------------------------------------------
extern "C" void kernel_launch(void* const* d_in, const int* in_sizes, int n_in,
                              void* d_out, int out_size)
{
    (void)in_sizes; (void)n_in; (void)out_size;

    const float* mod1 = (const float*)d_in[0];
    const float* mod2 = (const float*)d_in[1];
    const float* Wq  = (const float*)d_in[2];  const float* bq  = (const float*)d_in[3];
    const float* Wk  = (const float*)d_in[4];  const float* bk  = (const float*)d_in[5];
    const float* Wv  = (const float*)d_in[6];  const float* bv  = (const float*)d_in[7];
    const float* Wo  = (const float*)d_in[8];  const float* bo  = (const float*)d_in[9];
    const float* Ws  = (const float*)d_in[10]; const float* bs  = (const float*)d_in[11];
    const float* Wsh = (const float*)d_in[12]; const float* bsh = (const float*)d_in[13];
    float* out = (float*)d_out;

    float *pQ, *pK, *pV, *pS, *pH, *pO;
    cudaGetSymbolAddress((void**)&pQ, g_Q);
    cudaGetSymbolAddress((void**)&pK, g_K);
    cudaGetSymbolAddress((void**)&pV, g_V);
    cudaGetSymbolAddress((void**)&pS, g_S);
    cudaGetSymbolAddress((void**)&pH, g_H);
    cudaGetSymbolAddress((void**)&pO, g_O);

    dim3 gG(DD / 128, MTOT / 128);   // (4, 64)
    gemm_bf16x3<<<gG, 256>>>(mod1, Wq,  bq,  pQ);
    gemm_bf16x3<<<gG, 256>>>(mod2, Wk,  bk,  pK);
    gemm_bf16x3<<<gG, 256>>>(mod2, Wv,  bv,  pV);
    gemm_bf16x3<<<gG, 256>>>(mod2, Ws,  bs,  pS);
    gemm_bf16x3<<<gG, 256>>>(mod2, Wsh, bsh, pH);
    kvss_epilogue<<<(MTOT * DD) / (256 * 4), 256>>>(pK, pV, pS, pH);
    attn_bf16x3<<<dim3(SS / 64, HH, BB), 128>>>(pQ, pK, pV, pO);
    gemm_bf16x3<<<gG, 256>>>(pO, Wo, bo, out);
}

// round 3
// speedup vs baseline: 2.5802x; 1.4637x over previous
#include <cuda_runtime.h>
#include <cuda_bf16.h>
#include <cstdint>

#define BB 4
#define SS 2048
#define DD 512
#define HH 8
#define HDIM 64
#define MTOT 8192
#define KP 256            // k-pairs per 512-col row
#define NKVSH 2048

// ---------------- device scratch (pair-packed bf16x2 in u32) ----------------
__device__ __align__(16) uint32_t g_A1h[MTOT * KP], g_A1l[MTOT * KP];
__device__ __align__(16) uint32_t g_A2h[MTOT * KP], g_A2l[MTOT * KP];
__device__ __align__(16) uint32_t g_Wh[KP * (DD + NKVSH + DD)];
__device__ __align__(16) uint32_t g_Wl[KP * (DD + NKVSH + DD)];
__device__ __align__(16) uint32_t g_Qh[MTOT * KP], g_Ql[MTOT * KP];
__device__ __align__(16) float    g_KVSH[MTOT * NKVSH];
__device__ __align__(16) uint32_t g_KTh[32 * 32 * SS], g_KTl[32 * 32 * SS];     // [bh][dp 0..31][key 0..2047]
__device__ __align__(16) uint32_t g_Vph[32 * 1024 * 64], g_Vpl[32 * 1024 * 64]; // [bh][kp 0..1023][d 0..63]
__device__ __align__(16) uint32_t g_Oh[MTOT * KP], g_Ol[MTOT * KP];
__device__ __align__(16) float    g_bKVSH[NKVSH];

// weight pair-buffer offsets
#define WOFS_Q 0
#define WOFS_KVSH (KP * DD)
#define WOFS_O (KP * DD + KP * NKVSH)

// ---------------- helpers ----------------
__device__ __forceinline__ void split2(float x0, float x1, uint32_t& hi, uint32_t& lo)
{
    __nv_bfloat16 h0 = __float2bfloat16(x0);
    __nv_bfloat16 h1 = __float2bfloat16(x1);
    __nv_bfloat16 l0 = __float2bfloat16(x0 - __bfloat162float(h0));
    __nv_bfloat16 l1 = __float2bfloat16(x1 - __bfloat162float(h1));
    __nv_bfloat162 H; H.x = h0; H.y = h1;
    __nv_bfloat162 L; L.x = l0; L.y = l1;
    hi = *reinterpret_cast<uint32_t*>(&H);
    lo = *reinterpret_cast<uint32_t*>(&L);
}

__device__ __forceinline__ void mma16816(float c[4],
                                         uint32_t a0, uint32_t a1, uint32_t a2, uint32_t a3,
                                         uint32_t b0, uint32_t b1)
{
    asm volatile(
        "mma.sync.aligned.m16n8k16.row.col.f32.bf16.bf16.f32 "
        "{%0,%1,%2,%3}, {%4,%5,%6,%7}, {%8,%9}, {%0,%1,%2,%3};\n"
        : "+f"(c[0]), "+f"(c[1]), "+f"(c[2]), "+f"(c[3])
        : "r"(a0), "r"(a1), "r"(a2), "r"(a3), "r"(b0), "r"(b1));
}

__device__ __forceinline__ void cpa16(uint32_t* dst_smem, const uint32_t* src)
{
    uint32_t d = (uint32_t)__cvta_generic_to_shared(dst_smem);
    asm volatile("cp.async.cg.shared.global [%0], [%1], 16;\n" :: "r"(d), "l"(src));
}
__device__ __forceinline__ void cpa_commit() { asm volatile("cp.async.commit_group;\n"); }
__device__ __forceinline__ void cpa_wait_all() { asm volatile("cp.async.wait_group 0;\n"); }

// ---------------- conversion kernels ----------------
// rows: X[M][512] fp32 -> pairs [M][256] (pair = adjacent cols)
__global__ __launch_bounds__(256)
void conv_rows(const float* __restrict__ X, uint32_t* __restrict__ Oh, uint32_t* __restrict__ Ol)
{
    int id = blockIdx.x * 256 + threadIdx.x;   // 4 pairs each
    int fb = id * 8;
    float4 a = *(const float4*)&X[fb];
    float4 b = *(const float4*)&X[fb + 4];
    uint32_t h0, l0, h1, l1, h2, l2, h3, l3;
    split2(a.x, a.y, h0, l0);
    split2(a.z, a.w, h1, l1);
    split2(b.x, b.y, h2, l2);
    split2(b.z, b.w, h3, l3);
    int p = id * 4;
    Oh[p] = h0; Oh[p + 1] = h1; Oh[p + 2] = h2; Oh[p + 3] = h3;
    Ol[p] = l0; Ol[p + 1] = l1; Ol[p + 2] = l2; Ol[p + 3] = l3;
}

// cols: W[512][512] fp32 -> pairs across rows: out[kp][n] = {W[2kp][n], W[2kp+1][n]}
__global__ __launch_bounds__(256)
void conv_cols(const float* __restrict__ W, uint32_t* __restrict__ Oh,
               uint32_t* __restrict__ Ol, int ldo, int colofs)
{
    int id = blockIdx.x * 256 + threadIdx.x;   // (kp, n quad)
    int kp = id >> 7;
    int n4 = (id & 127) << 2;
    float4 r0 = *(const float4*)&W[(2 * kp) * DD + n4];
    float4 r1 = *(const float4*)&W[(2 * kp + 1) * DD + n4];
    uint32_t h, l;
    int base = kp * ldo + colofs + n4;
    split2(r0.x, r1.x, h, l); Oh[base + 0] = h; Ol[base + 0] = l;
    split2(r0.y, r1.y, h, l); Oh[base + 1] = h; Ol[base + 1] = l;
    split2(r0.z, r1.z, h, l); Oh[base + 2] = h; Ol[base + 2] = l;
    split2(r0.w, r1.w, h, l); Oh[base + 3] = h; Ol[base + 3] = l;
}

__global__ void bias_pack(const float* bk, const float* bv, const float* bs, const float* bsh)
{
    int i = blockIdx.x * 256 + threadIdx.x;  // 0..2047
    float v;
    int sec = i >> 9, j = i & 511;
    if (sec == 0) v = bk[j];
    else if (sec == 1) v = bv[j];
    else if (sec == 2) v = bs[j];
    else v = bsh[j];
    g_bKVSH[i] = v;
}

// ---------------- GEMM on pre-split pairs ----------------
// C[M][NB] = A[M][512] @ W[512][NB] + bias (bf16x3)
// block 128x128, 256 thr, 8 warps (2x4), warp tile 64x32, ktile = 16 kp (32 k)
#define GLDA 20
#define GLDB 136

template<int EPI>   // 0: fp32 C, 1: pair store (Ch/Cl)
__global__ __launch_bounds__(256, 2)
void gemm_pairs(const uint32_t* __restrict__ Ah, const uint32_t* __restrict__ Al,
                const uint32_t* __restrict__ Bh, const uint32_t* __restrict__ Bl,
                int NB, const float* __restrict__ bias,
                float* __restrict__ C, uint32_t* __restrict__ Ch, uint32_t* __restrict__ Cl)
{
    extern __shared__ uint32_t sm[];
    uint32_t* sAh = sm;                         // [2][128*GLDA]
    uint32_t* sAl = sAh + 2 * 128 * GLDA;
    uint32_t* sBh = sAl + 2 * 128 * GLDA;       // [2][16*GLDB]
    uint32_t* sBl = sBh + 2 * 16 * GLDB;

    const int m0 = blockIdx.y * 128;
    const int n0b = blockIdx.x * 128;
    const int tid = threadIdx.x;
    const int warp = tid >> 5;
    const int lane = tid & 31;
    const int g = lane >> 2;
    const int tig = lane & 3;
    const int wm = (warp >> 2) * 64;
    const int wn = (warp & 3) * 32;

    float acc[4][4][4];
#pragma unroll
    for (int mt = 0; mt < 4; ++mt)
#pragma unroll
        for (int nt = 0; nt < 4; ++nt)
#pragma unroll
            for (int r = 0; r < 4; ++r) acc[mt][nt][r] = 0.f;

    auto loadTile = [&](int kt, int buf) {
        int kp0 = kt * 16;
#pragma unroll
        for (int it = 0; it < 2; ++it) {
            int id = it * 256 + tid;
            int r = id >> 2, ch = (id & 3) << 2;
            int so = buf * 128 * GLDA + r * GLDA + ch;
            int go = (m0 + r) * KP + kp0 + ch;
            cpa16(&sAh[so], &Ah[go]);
            cpa16(&sAl[so], &Al[go]);
        }
#pragma unroll
        for (int it = 0; it < 2; ++it) {
            int id = it * 256 + tid;
            int kp = id >> 5, ch = (id & 31) << 2;
            int so = buf * 16 * GLDB + kp * GLDB + ch;
            int go = (kp0 + kp) * NB + n0b + ch;
            cpa16(&sBh[so], &Bh[go]);
            cpa16(&sBl[so], &Bl[go]);
        }
    };

    loadTile(0, 0);
    cpa_commit();

    for (int kt = 0; kt < 16; ++kt) {
        cpa_wait_all();
        __syncthreads();
        if (kt + 1 < 16) { loadTile(kt + 1, (kt + 1) & 1); cpa_commit(); }
        const int buf = kt & 1;
        const int aB = buf * 128 * GLDA;
        const int bB = buf * 16 * GLDB;
#pragma unroll
        for (int s = 0; s < 2; ++s) {
            uint32_t ah[4][4], al[4][4], bh[4][2], bl[4][2];
#pragma unroll
            for (int mt = 0; mt < 4; ++mt) {
                int r0 = aB + (wm + mt * 16 + g) * GLDA + s * 8;
                int r1 = aB + (wm + mt * 16 + g + 8) * GLDA + s * 8;
                ah[mt][0] = sAh[r0 + tig];   ah[mt][1] = sAh[r1 + tig];
                ah[mt][2] = sAh[r0 + tig + 4]; ah[mt][3] = sAh[r1 + tig + 4];
                al[mt][0] = sAl[r0 + tig];   al[mt][1] = sAl[r1 + tig];
                al[mt][2] = sAl[r0 + tig + 4]; al[mt][3] = sAl[r1 + tig + 4];
            }
#pragma unroll
            for (int nt = 0; nt < 4; ++nt) {
                int col = wn + nt * 8 + g;
                int b0 = bB + (s * 8 + tig) * GLDB + col;
                int b1 = bB + (s * 8 + tig + 4) * GLDB + col;
                bh[nt][0] = sBh[b0]; bh[nt][1] = sBh[b1];
                bl[nt][0] = sBl[b0]; bl[nt][1] = sBl[b1];
            }
#pragma unroll
            for (int mt = 0; mt < 4; ++mt)
#pragma unroll
                for (int nt = 0; nt < 4; ++nt) {
                    mma16816(acc[mt][nt], ah[mt][0], ah[mt][1], ah[mt][2], ah[mt][3],
                             bh[nt][0], bh[nt][1]);
                    mma16816(acc[mt][nt], ah[mt][0], ah[mt][1], ah[mt][2], ah[mt][3],
                             bl[nt][0], bl[nt][1]);
                    mma16816(acc[mt][nt], al[mt][0], al[mt][1], al[mt][2], al[mt][3],
                             bh[nt][0], bh[nt][1]);
                }
        }
    }

#pragma unroll
    for (int mt = 0; mt < 4; ++mt) {
        int row0 = m0 + wm + mt * 16 + g;
        int row1 = row0 + 8;
#pragma unroll
        for (int nt = 0; nt < 4; ++nt) {
            int col = n0b + wn + nt * 8 + 2 * tig;
            float b0 = bias[col], b1 = bias[col + 1];
            if (EPI == 0) {
                *(float2*)&C[row0 * NB + col] =
                    make_float2(acc[mt][nt][0] + b0, acc[mt][nt][1] + b1);
                *(float2*)&C[row1 * NB + col] =
                    make_float2(acc[mt][nt][2] + b0, acc[mt][nt][3] + b1);
            } else {
                int dpi = col >> 1;
                uint32_t hh, ll;
                split2(acc[mt][nt][0] + b0, acc[mt][nt][1] + b1, hh, ll);
                Ch[row0 * KP + dpi] = hh; Cl[row0 * KP + dpi] = ll;
                split2(acc[mt][nt][2] + b0, acc[mt][nt][3] + b1, hh, ll);
                Ch[row1 * KP + dpi] = hh; Cl[row1 * KP + dpi] = ll;
            }
        }
    }
}

// ---------------- KVSH -> K', V' pack into attention layouts ----------------
// grid (HH, 128): block = (head h, 64-key tile kb); 256 threads
__global__ __launch_bounds__(256)
void kvss_pack()
{
    const int h = blockIdx.x;
    const int kb = blockIdx.y;
    const int b = kb >> 5;
    const int key0 = (kb & 31) * 64;
    const int bh = b * HH + h;
    const int tid = threadIdx.x;
    const int c = (tid & 15) << 2;   // 0..60 within head

#pragma unroll
    for (int it = 0; it < 2; ++it) {
        int kpl = (tid >> 4) + it * 16;   // 0..31
        int r = b * SS + key0 + 2 * kpl;
        const float* base0 = &g_KVSH[(size_t)r * NKVSH];
        const float* base1 = base0 + NKVSH;
        int co = h * 64 + c;
        float4 k0 = *(const float4*)&base0[co];
        float4 k1 = *(const float4*)&base1[co];
        float4 v0 = *(const float4*)&base0[512 + co];
        float4 v1 = *(const float4*)&base1[512 + co];
        float4 s0 = *(const float4*)&base0[1024 + co];
        float4 s1 = *(const float4*)&base1[1024 + co];
        float4 t0 = *(const float4*)&base0[1536 + co];
        float4 t1 = *(const float4*)&base1[1536 + co];

        float K0[4] = {fmaf(k0.x, s0.x, t0.x), fmaf(k0.y, s0.y, t0.y),
                       fmaf(k0.z, s0.z, t0.z), fmaf(k0.w, s0.w, t0.w)};
        float K1[4] = {fmaf(k1.x, s1.x, t1.x), fmaf(k1.y, s1.y, t1.y),
                       fmaf(k1.z, s1.z, t1.z), fmaf(k1.w, s1.w, t1.w)};
        float V0[4] = {fmaf(v0.x, s0.x, t0.x), fmaf(v0.y, s0.y, t0.y),
                       fmaf(v0.z, s0.z, t0.z), fmaf(v0.w, s0.w, t0.w)};
        float V1[4] = {fmaf(v1.x, s1.x, t1.x), fmaf(v1.y, s1.y, t1.y),
                       fmaf(v1.z, s1.z, t1.z), fmaf(v1.w, s1.w, t1.w)};

        // V pairs (across adjacent keys): [bh][kp][d]
        {
            int kpg = (key0 >> 1) + kpl;
            uint32_t vh[4], vl[4];
            split2(V0[0], V1[0], vh[0], vl[0]);
            split2(V0[1], V1[1], vh[1], vl[1]);
            split2(V0[2], V1[2], vh[2], vl[2]);
            split2(V0[3], V1[3], vh[3], vl[3]);
            size_t o = ((size_t)bh * 1024 + kpg) * 64 + c;
            *(uint4*)&g_Vph[o] = make_uint4(vh[0], vh[1], vh[2], vh[3]);
            *(uint4*)&g_Vpl[o] = make_uint4(vl[0], vl[1], vl[2], vl[3]);
        }
        // K^T pairs (across adjacent d): [bh][dp][key]
        {
            int key = key0 + 2 * kpl;
#pragma unroll
            for (int jp = 0; jp < 2; ++jp) {
                int dp = (c >> 1) + jp;
                uint32_t h0_, l0_, h1_, l1_;
                split2(K0[2 * jp], K0[2 * jp + 1], h0_, l0_);
                split2(K1[2 * jp], K1[2 * jp + 1], h1_, l1_);
                size_t o = ((size_t)bh * 32 + dp) * SS + key;
                *(uint2*)&g_KTh[o] = make_uint2(h0_, h1_);
                *(uint2*)&g_KTl[o] = make_uint2(l0_, l1_);
            }
        }
    }
}

// ---------------- Flash attention on pre-split pairs ----------------
// block = (b, h, 64 q rows), 128 threads (4 warps x 16 q rows), key chunk 64
#define ALDT 72
#define ALDP 36

__global__ __launch_bounds__(128)
void attn_pairs()
{
    extern __shared__ uint32_t sm[];
    uint32_t* Kh = sm;                 // [32][ALDT]
    uint32_t* Kl = Kh + 32 * ALDT;
    uint32_t* Vh = Kl + 32 * ALDT;     // [32][ALDT]
    uint32_t* Vl = Vh + 32 * ALDT;
    uint32_t* Ph = Vl + 32 * ALDT;     // [64][ALDP]
    uint32_t* Pl = Ph + 64 * ALDP;

    const int b = blockIdx.z;
    const int h = blockIdx.y;
    const int bh = b * HH + h;
    const int q0 = blockIdx.x * 64;
    const int rowbase = b * SS;
    const int tid = threadIdx.x;
    const int warp = tid >> 5;
    const int lane = tid & 31;
    const int g = lane >> 2;
    const int tig = lane & 3;

    const uint32_t* KTh = &g_KTh[(size_t)bh * 32 * SS];
    const uint32_t* KTl = &g_KTl[(size_t)bh * 32 * SS];
    const uint32_t* Vph = &g_Vph[(size_t)bh * 1024 * 64];
    const uint32_t* Vpl = &g_Vpl[(size_t)bh * 1024 * 64];

    // Q fragments from pair buffer
    uint32_t qh[4][4], ql[4][4];
    {
        size_t r0 = (size_t)(rowbase + q0 + warp * 16 + g) * KP + h * 32;
        size_t r1 = r0 + 8 * KP;
#pragma unroll
        for (int s = 0; s < 4; ++s) {
            qh[s][0] = g_Qh[r0 + s * 8 + tig];
            qh[s][1] = g_Qh[r1 + s * 8 + tig];
            qh[s][2] = g_Qh[r0 + s * 8 + tig + 4];
            qh[s][3] = g_Qh[r1 + s * 8 + tig + 4];
            ql[s][0] = g_Ql[r0 + s * 8 + tig];
            ql[s][1] = g_Ql[r1 + s * 8 + tig];
            ql[s][2] = g_Ql[r0 + s * 8 + tig + 4];
            ql[s][3] = g_Ql[r1 + s * 8 + tig + 4];
        }
    }

    auto loadKT = [&](int cidx) {
#pragma unroll
        for (int it = 0; it < 4; ++it) {
            int id = it * 128 + tid;
            int r = id >> 4, ch = (id & 15) << 2;
            int so = r * ALDT + ch;
            size_t go = (size_t)r * SS + cidx * 64 + ch;
            cpa16(&Kh[so], &KTh[go]);
            cpa16(&Kl[so], &KTl[go]);
        }
    };
    auto loadV = [&](int cidx) {
#pragma unroll
        for (int it = 0; it < 4; ++it) {
            int id = it * 128 + tid;
            int r = id >> 4, ch = (id & 15) << 2;
            int so = r * ALDT + ch;
            size_t go = (size_t)(cidx * 32 + r) * 64 + ch;
            cpa16(&Vh[so], &Vph[go]);
            cpa16(&Vl[so], &Vpl[go]);
        }
    };

    float o[8][4];
#pragma unroll
    for (int nt = 0; nt < 8; ++nt)
#pragma unroll
        for (int r = 0; r < 4; ++r) o[nt][r] = 0.f;
    float mA = -1e30f, mB = -1e30f, lA = 0.f, lB = 0.f;

    const int prow0 = (warp * 16 + g) * ALDP;
    const int prow1 = (warp * 16 + g + 8) * ALDP;

    loadKT(0);
    cpa_commit();

    for (int c = 0; c < 32; ++c) {
        cpa_wait_all();
        __syncthreads();              // KT(c) ready; all prev PV readers done
        loadV(c);
        cpa_commit();

        // S = Q @ K^T
        float s[8][4];
#pragma unroll
        for (int nt = 0; nt < 8; ++nt)
#pragma unroll
            for (int r = 0; r < 4; ++r) s[nt][r] = 0.f;
#pragma unroll
        for (int ks = 0; ks < 4; ++ks) {
#pragma unroll
            for (int nt = 0; nt < 8; ++nt) {
                int col = nt * 8 + g;
                uint32_t b0h = Kh[(8 * ks + tig) * ALDT + col];
                uint32_t b1h = Kh[(8 * ks + tig + 4) * ALDT + col];
                uint32_t b0l = Kl[(8 * ks + tig) * ALDT + col];
                uint32_t b1l = Kl[(8 * ks + tig + 4) * ALDT + col];
                mma16816(s[nt], qh[ks][0], qh[ks][1], qh[ks][2], qh[ks][3], b0h, b1h);
                mma16816(s[nt], qh[ks][0], qh[ks][1], qh[ks][2], qh[ks][3], b0l, b1l);
                mma16816(s[nt], ql[ks][0], ql[ks][1], ql[ks][2], ql[ks][3], b0h, b1h);
            }
        }

        // online softmax
        const float sc = 0.125f;
        float rmA = -1e30f, rmB = -1e30f;
#pragma unroll
        for (int nt = 0; nt < 8; ++nt) {
            s[nt][0] *= sc; s[nt][1] *= sc; s[nt][2] *= sc; s[nt][3] *= sc;
            rmA = fmaxf(rmA, fmaxf(s[nt][0], s[nt][1]));
            rmB = fmaxf(rmB, fmaxf(s[nt][2], s[nt][3]));
        }
        rmA = fmaxf(rmA, __shfl_xor_sync(0xffffffffu, rmA, 1));
        rmA = fmaxf(rmA, __shfl_xor_sync(0xffffffffu, rmA, 2));
        rmB = fmaxf(rmB, __shfl_xor_sync(0xffffffffu, rmB, 1));
        rmB = fmaxf(rmB, __shfl_xor_sync(0xffffffffu, rmB, 2));

        float mnA = fmaxf(mA, rmA);
        float mnB = fmaxf(mB, rmB);
        float alA = __expf(mA - mnA);
        float alB = __expf(mB - mnB);
        mA = mnA; mB = mnB;

        float sumA = 0.f, sumB = 0.f;
#pragma unroll
        for (int nt = 0; nt < 8; ++nt) {
            float p0 = __expf(s[nt][0] - mA);
            float p1 = __expf(s[nt][1] - mA);
            float p2 = __expf(s[nt][2] - mB);
            float p3 = __expf(s[nt][3] - mB);
            sumA += p0 + p1;
            sumB += p2 + p3;
            uint32_t hh, ll;
            split2(p0, p1, hh, ll);
            Ph[prow0 + nt * 4 + tig] = hh; Pl[prow0 + nt * 4 + tig] = ll;
            split2(p2, p3, hh, ll);
            Ph[prow1 + nt * 4 + tig] = hh; Pl[prow1 + nt * 4 + tig] = ll;
        }
        sumA += __shfl_xor_sync(0xffffffffu, sumA, 1);
        sumA += __shfl_xor_sync(0xffffffffu, sumA, 2);
        sumB += __shfl_xor_sync(0xffffffffu, sumB, 1);
        sumB += __shfl_xor_sync(0xffffffffu, sumB, 2);
        lA = lA * alA + sumA;
        lB = lB * alB + sumB;
#pragma unroll
        for (int nt = 0; nt < 8; ++nt) {
            o[nt][0] *= alA; o[nt][1] *= alA;
            o[nt][2] *= alB; o[nt][3] *= alB;
        }

        cpa_wait_all();
        __syncthreads();              // V(c) ready; P visible; S-mma done with KT
        if (c + 1 < 32) { loadKT(c + 1); cpa_commit(); }

        // O += P @ V
#pragma unroll
        for (int ks = 0; ks < 4; ++ks) {
            uint32_t pah[4], pal[4];
            pah[0] = Ph[prow0 + 8 * ks + tig];
            pah[1] = Ph[prow1 + 8 * ks + tig];
            pah[2] = Ph[prow0 + 8 * ks + tig + 4];
            pah[3] = Ph[prow1 + 8 * ks + tig + 4];
            pal[0] = Pl[prow0 + 8 * ks + tig];
            pal[1] = Pl[prow1 + 8 * ks + tig];
            pal[2] = Pl[prow0 + 8 * ks + tig + 4];
            pal[3] = Pl[prow1 + 8 * ks + tig + 4];
#pragma unroll
            for (int nt = 0; nt < 8; ++nt) {
                int col = nt * 8 + g;
                uint32_t b0h = Vh[(8 * ks + tig) * ALDT + col];
                uint32_t b1h = Vh[(8 * ks + tig + 4) * ALDT + col];
                uint32_t b0l = Vl[(8 * ks + tig) * ALDT + col];
                uint32_t b1l = Vl[(8 * ks + tig + 4) * ALDT + col];
                mma16816(o[nt], pah[0], pah[1], pah[2], pah[3], b0h, b1h);
                mma16816(o[nt], pah[0], pah[1], pah[2], pah[3], b0l, b1l);
                mma16816(o[nt], pal[0], pal[1], pal[2], pal[3], b0h, b1h);
            }
        }
    }

    // normalize + store as pairs (input layout for O-projection gemm)
    float invA = 1.f / lA;
    float invB = 1.f / lB;
    size_t r0 = (size_t)(rowbase + q0 + warp * 16 + g) * KP + h * 32;
    size_t r1 = r0 + 8 * KP;
#pragma unroll
    for (int nt = 0; nt < 8; ++nt) {
        int dpi = nt * 4 + tig;
        uint32_t hh, ll;
        split2(o[nt][0] * invA, o[nt][1] * invA, hh, ll);
        g_Oh[r0 + dpi] = hh; g_Ol[r0 + dpi] = ll;
        split2(o[nt][2] * invB, o[nt][3] * invB, hh, ll);
        g_Oh[r1 + dpi] = hh; g_Ol[r1 + dpi] = ll;
    }
}

// ---------------------------------------------------------------------------
extern "C" void kernel_launch(void* const* d_in, const int* in_sizes, int n_in,
                              void* d_out, int out_size)
{
    (void)in_sizes; (void)n_in; (void)out_size;

    const float* mod1 = (const float*)d_in[0];
    const float* mod2 = (const float*)d_in[1];
    const float* Wq  = (const float*)d_in[2];  const float* bq  = (const float*)d_in[3];
    const float* Wk  = (const float*)d_in[4];  const float* bk  = (const float*)d_in[5];
    const float* Wv  = (const float*)d_in[6];  const float* bv  = (const float*)d_in[7];
    const float* Wo  = (const float*)d_in[8];  const float* bo  = (const float*)d_in[9];
    const float* Ws  = (const float*)d_in[10]; const float* bs  = (const float*)d_in[11];
    const float* Wsh = (const float*)d_in[12]; const float* bsh = (const float*)d_in[13];
    float* out = (float*)d_out;

    uint32_t *pA1h, *pA1l, *pA2h, *pA2l, *pWh, *pWl, *pQh, *pQl, *pOh, *pOl;
    float *pKVSH, *pbK;
    cudaGetSymbolAddress((void**)&pA1h, g_A1h);
    cudaGetSymbolAddress((void**)&pA1l, g_A1l);
    cudaGetSymbolAddress((void**)&pA2h, g_A2h);
    cudaGetSymbolAddress((void**)&pA2l, g_A2l);
    cudaGetSymbolAddress((void**)&pWh, g_Wh);
    cudaGetSymbolAddress((void**)&pWl, g_Wl);
    cudaGetSymbolAddress((void**)&pQh, g_Qh);
    cudaGetSymbolAddress((void**)&pQl, g_Ql);
    cudaGetSymbolAddress((void**)&pOh, g_Oh);
    cudaGetSymbolAddress((void**)&pOl, g_Ol);
    cudaGetSymbolAddress((void**)&pKVSH, g_KVSH);
    cudaGetSymbolAddress((void**)&pbK, g_bKVSH);

    // opt-in to >48KB dynamic smem (idempotent)
    const int GEMM_SMEM = (2 * 128 * GLDA * 2 + 2 * 16 * GLDB * 2) * 4;  // 75776 B
    const int ATTN_SMEM = (4 * 32 * ALDT + 2 * 64 * ALDP) * 4;           // 55296 B
    cudaFuncSetAttribute(gemm_pairs<0>, cudaFuncAttributeMaxDynamicSharedMemorySize, GEMM_SMEM);
    cudaFuncSetAttribute(gemm_pairs<1>, cudaFuncAttributeMaxDynamicSharedMemorySize, GEMM_SMEM);
    cudaFuncSetAttribute(attn_pairs, cudaFuncAttributeMaxDynamicSharedMemorySize, ATTN_SMEM);

    // 1) conversions
    conv_rows<<<MTOT * KP / 4 / 256, 256>>>(mod1, pA1h, pA1l);
    conv_rows<<<MTOT * KP / 4 / 256, 256>>>(mod2, pA2h, pA2l);
    conv_cols<<<128, 256>>>(Wq,  pWh + WOFS_Q,    pWl + WOFS_Q,    DD,    0);
    conv_cols<<<128, 256>>>(Wk,  pWh + WOFS_KVSH, pWl + WOFS_KVSH, NKVSH, 0);
    conv_cols<<<128, 256>>>(Wv,  pWh + WOFS_KVSH, pWl + WOFS_KVSH, NKVSH, 512);
    conv_cols<<<128, 256>>>(Ws,  pWh + WOFS_KVSH, pWl + WOFS_KVSH, NKVSH, 1024);
    conv_cols<<<128, 256>>>(Wsh, pWh + WOFS_KVSH, pWl + WOFS_KVSH, NKVSH, 1536);
    conv_cols<<<128, 256>>>(Wo,  pWh + WOFS_O,    pWl + WOFS_O,    DD,    0);
    bias_pack<<<8, 256>>>(bk, bv, bs, bsh);

    // 2) Q projection (pair output)
    gemm_pairs<1><<<dim3(DD / 128, MTOT / 128), 256, GEMM_SMEM>>>(
        pA1h, pA1l, pWh + WOFS_Q, pWl + WOFS_Q, DD, bq, nullptr, pQh, pQl);

    // 3) merged K|V|S|H projection (fp32 output)
    gemm_pairs<0><<<dim3(NKVSH / 128, MTOT / 128), 256, GEMM_SMEM>>>(
        pA2h, pA2l, pWh + WOFS_KVSH, pWl + WOFS_KVSH, NKVSH, pbK, pKVSH, nullptr, nullptr);

    // 4) apply scale/shift + pack attention layouts
    kvss_pack<<<dim3(HH, 128), 256>>>();

    // 5) attention (pair output)
    attn_pairs<<<dim3(SS / 64, HH, BB), 128, ATTN_SMEM>>>();

    // 6) output projection
    gemm_pairs<0><<<dim3(DD / 128, MTOT / 128), 256, GEMM_SMEM>>>(
        pOh, pOl, pWh + WOFS_O, pWl + WOFS_O, DD, bo, out, nullptr, nullptr);
}